// round 15
// baseline (speedup 1.0000x reference)
#include <cuda_runtime.h>
#include <cuda_bf16.h>
#include <cstdint>

#define D     256
#define NB    30
#define EG    240
#define BG    2048
#define GAUX  8
#define AST   520     // A row stride (bf16 elems): 1040B = 260 words = 4 mod 32 banks
#define H32ST 257     // fp32 h row stride

__device__ float g_Mgeo[5 * D];
__device__ float g_Msem[11 * D];
__device__ float g_bias0[D];
__device__ float g_gbuf[BG * 4 * D];
// B fragments, exact per-thread mma layout:
// id = (((l*2+p)*32 + kstep)*32 + ntile)*32 + lane  ->  u64 {b1,b0}
__device__ unsigned long long g_Bfrag[3 * 2 * 32 * 32 * 32];

// d = a @ b + d   (m16n8k16, bf16 in, f32 accum)
#define MMA16816(d, a, b0_, b1_) \
    asm volatile("mma.sync.aligned.m16n8k16.row.col.f32.bf16.bf16.f32 " \
                 "{%0,%1,%2,%3}, {%4,%5,%6,%7}, {%8,%9}, {%0,%1,%2,%3};" \
                 : "+f"((d)[0]), "+f"((d)[1]), "+f"((d)[2]), "+f"((d)[3]) \
                 : "r"((a)[0]), "r"((a)[1]), "r"((a)[2]), "r"((a)[3]), \
                   "r"(b0_), "r"(b1_))

__device__ __forceinline__ unsigned short bfhi(float x) {
    return __bfloat16_as_ushort(__float2bfloat16_rn(x));
}
__device__ __forceinline__ unsigned short bflo(float x) {
    float h = __bfloat162float(__float2bfloat16_rn(x));
    return __bfloat16_as_ushort(__float2bfloat16_rn(x - h));
}

// ---------------------------------------------------------------------------
// init: blocks 0..16 = folded input MLP; blocks 17.. = B-fragment packing
// ---------------------------------------------------------------------------
__global__ void init_kernel(const float* __restrict__ Wgeo,
                            const float* __restrict__ bgeo,
                            const float* __restrict__ emb,
                            const float* __restrict__ Wlot,
                            const float* __restrict__ blot,
                            const float* __restrict__ W1,
                            const float* __restrict__ W2,
                            const float* __restrict__ W3)
{
    int b = blockIdx.x;
    if (b < 17) {
        int c = threadIdx.x;
        int r = b;
        float a0 = 0.f, a1 = 0.f, a2 = 0.f, a3 = 0.f;
        if (r < 5) {
            for (int j = 0; j < D; j += 4) {
                a0 = fmaf(Wgeo[r * D + j + 0], Wlot[(j + 0) * D + c], a0);
                a1 = fmaf(Wgeo[r * D + j + 1], Wlot[(j + 1) * D + c], a1);
                a2 = fmaf(Wgeo[r * D + j + 2], Wlot[(j + 2) * D + c], a2);
                a3 = fmaf(Wgeo[r * D + j + 3], Wlot[(j + 3) * D + c], a3);
            }
            g_Mgeo[r * D + c] = (a0 + a1) + (a2 + a3);
        } else if (r < 16) {
            int s = r - 5;
            for (int j = 0; j < D; j += 4) {
                a0 = fmaf(emb[s * D + j + 0], Wlot[(D + j + 0) * D + c], a0);
                a1 = fmaf(emb[s * D + j + 1], Wlot[(D + j + 1) * D + c], a1);
                a2 = fmaf(emb[s * D + j + 2], Wlot[(D + j + 2) * D + c], a2);
                a3 = fmaf(emb[s * D + j + 3], Wlot[(D + j + 3) * D + c], a3);
            }
            g_Msem[s * D + c] = (a0 + a1) + (a2 + a3);
        } else {
            for (int j = 0; j < D; j += 4) {
                a0 = fmaf(bgeo[j + 0], Wlot[(j + 0) * D + c], a0);
                a1 = fmaf(bgeo[j + 1], Wlot[(j + 1) * D + c], a1);
                a2 = fmaf(bgeo[j + 2], Wlot[(j + 2) * D + c], a2);
                a3 = fmaf(bgeo[j + 3], Wlot[(j + 3) * D + c], a3);
            }
            g_bias0[c] = blot[c] + (a0 + a1) + (a2 + a3);
        }
        return;
    }
    // B-fragment pack: one u64 per thread
    int id = (b - 17) * 256 + threadIdx.x;       // < 196608
    int t  = id & 31;
    int nt = (id >> 5) & 31;
    int ks = (id >> 10) & 31;
    int p  = (id >> 15) & 1;
    int l  = id >> 16;
    const float* W = (l == 0) ? W1 : (l == 1) ? W2 : W3;   // [512][256]
    int gq = t >> 2, lq = t & 3;
    int n  = nt * 8 + gq;
    int k0 = ks * 16 + 2 * lq;
    float v00 = W[(k0 + 0) * D + n], v01 = W[(k0 + 1) * D + n];
    float v10 = W[(k0 + 8) * D + n], v11 = W[(k0 + 9) * D + n];
    unsigned short s00, s01, s10, s11;
    if (p == 0) { s00 = bfhi(v00); s01 = bfhi(v01); s10 = bfhi(v10); s11 = bfhi(v11); }
    else        { s00 = bflo(v00); s01 = bflo(v01); s10 = bflo(v10); s11 = bflo(v11); }
    unsigned int b0 = ((unsigned int)s01 << 16) | s00;
    unsigned int b1 = ((unsigned int)s11 << 16) | s10;
    g_Bfrag[id] = ((unsigned long long)b1 << 32) | b0;
}

// ---------------------------------------------------------------------------
// Main kernel: 2 graphs per CTA (M=64 rows: 0-31 graph A, 32-63 graph B).
// 256 threads = 8 warps; warp w owns cols [32w,32w+32) x all 64 rows
// (4 m-tiles x 4 n-tiles of m16n8k16). Split-bf16 GEMM: AhBh + AlBh + AhBl.
// ---------------------------------------------------------------------------
__global__ void __launch_bounds__(256, 1)
graph_kernel(const float* __restrict__ geometry,
             const int*   __restrict__ semantic,
             const int*   __restrict__ e_src,
             const int*   __restrict__ e_dst,
             const float* __restrict__ Wlot,
             const float* __restrict__ bmp1,
             const float* __restrict__ bmp2,
             const float* __restrict__ bmp3)
{
    extern __shared__ char smem[];
    __nv_bfloat16* sA_hi = (__nv_bfloat16*)smem;                   // 64*AST
    __nv_bfloat16* sA_lo = sA_hi + 64 * AST;                       // 64*AST
    float* h32   = (float*)(smem + 2 * 64 * AST * 2);              // 64*H32ST
    int*   s_cnt = (int*)(h32 + 64 * H32ST);                       // 64
    int*   s_off = s_cnt + 64;                                     // 64
    int*   s_cur = s_off + 64;                                     // 64
    int*   s_sem = s_cur + 64;                                     // 64
    int*   s_list = s_sem + 64;                                    // 480
    float* s_inv = (float*)(s_list + 480);                         // 64
    float* s_geo = s_inv + 64;                                     // 300

    const int blk  = blockIdx.x;     // graph pair: graphs 2blk, 2blk+1
    const int tid  = threadIdx.x;
    const int w    = tid >> 5;
    const int lane = tid & 31;
    const int gq   = lane >> 2;
    const int lq   = lane & 3;

    // ---- per-graph data ----
    for (int i = tid; i < 2 * NB * 5; i += 256) s_geo[i] = geometry[blk * 300 + i];
    if (tid < 2 * NB) s_sem[tid] = semantic[blk * 2 * NB + tid];
    if (tid < 64) s_cnt[tid] = 0;
    __syncthreads();
    for (int e = tid; e < 2 * EG; e += 256) {
        int gi = e / EG, ei = e - gi * EG;
        int d = e_dst[(2 * blk + gi) * EG + ei] - (2 * blk + gi) * NB;
        atomicAdd(&s_cnt[gi * 32 + d], 1);
    }
    __syncthreads();
    if (tid == 0) {
        for (int gi = 0; gi < 2; gi++) {
            int a = 0;
            for (int n = 0; n < NB; n++) {
                s_off[gi * 32 + n] = a; s_cur[gi * 32 + n] = a;
                a += s_cnt[gi * 32 + n];
            }
        }
    }
    if (tid < 64) {
        int n = tid & 31;
        s_inv[tid] = (n < NB && s_cnt[tid]) ? 1.0f / (float)s_cnt[tid] : 0.0f;
    }
    __syncthreads();
    for (int e = tid; e < 2 * EG; e += 256) {
        int gi = e / EG, ei = e - gi * EG;
        int s = e_src[(2 * blk + gi) * EG + ei] - (2 * blk + gi) * NB;
        int d = e_dst[(2 * blk + gi) * EG + ei] - (2 * blk + gi) * NB;
        int p = atomicAdd(&s_cur[gi * 32 + d], 1);
        s_list[gi * EG + p] = s;
    }

    // ---- h0: thread = column c ----
    {
        const int c = tid;
        float mg0 = g_Mgeo[0 * D + c], mg1 = g_Mgeo[1 * D + c];
        float mg2 = g_Mgeo[2 * D + c], mg3 = g_Mgeo[3 * D + c];
        float mg4 = g_Mgeo[4 * D + c];
        const float bb = g_bias0[c];
        float mA = 0.f, mB = 0.f;
        #pragma unroll 4
        for (int r = 0; r < 64; r++) {
            int gi = r >> 5, n = r & 31;
            float v = 0.f;
            if (n < NB) {
                v = bb + Wlot[(2 * D + n) * D + c] + g_Msem[s_sem[gi * NB + n] * D + c];
                const float* ge = s_geo + gi * 150 + n * 5;
                v = fmaf(ge[0], mg0, v); v = fmaf(ge[1], mg1, v);
                v = fmaf(ge[2], mg2, v); v = fmaf(ge[3], mg3, v);
                v = fmaf(ge[4], mg4, v);
                v = fmaxf(v, 0.f);
            }
            h32[r * H32ST + c] = v;
            unsigned short hb = bfhi(v);
            sA_hi[r * AST + c] = __ushort_as_bfloat16(hb);
            sA_lo[r * AST + c] = __float2bfloat16_rn(
                v - __bfloat162float(__ushort_as_bfloat16(hb)));
            if (gi == 0) mA = fmaxf(mA, v); else mB = fmaxf(mB, v);
        }
        g_gbuf[(2 * blk + 0) * 1024 + c] = mA;
        g_gbuf[(2 * blk + 1) * 1024 + c] = mB;
    }
    __syncthreads();

    // ---- 3 message-passing layers ----
    for (int l = 0; l < 3; l++) {
        // gather: thread = column c; xa into A cols [256,512)
        {
            const int c = tid;
            #pragma unroll 4
            for (int r = 0; r < 64; r++) {
                int gi = r >> 5, n = r & 31;
                float x = 0.f;
                if (n < NB) {
                    int cnt = s_cnt[gi * 32 + n];
                    if (cnt) {
                        int e0 = s_off[gi * 32 + n], e1 = e0 + cnt;
                        for (int e = e0; e < e1; e++) {
                            int srow = gi * 32 + s_list[gi * EG + e];
                            x += h32[srow * H32ST + c];
                        }
                        x *= s_inv[gi * 32 + n];
                    }
                }
                unsigned short hb = bfhi(x);
                sA_hi[r * AST + D + c] = __ushort_as_bfloat16(hb);
                sA_lo[r * AST + D + c] = __float2bfloat16_rn(
                    x - __bfloat162float(__ushort_as_bfloat16(hb)));
            }
        }
        __syncthreads();

        // GEMM: C[64][256] = A[64][512] @ W[512][256], split-bf16, 3 passes
        float acc[4][4][4];
        #pragma unroll
        for (int mt = 0; mt < 4; mt++)
            #pragma unroll
            for (int j = 0; j < 4; j++)
                #pragma unroll
                for (int r = 0; r < 4; r++) acc[mt][j][r] = 0.f;

        #pragma unroll 1
        for (int pass = 0; pass < 3; pass++) {
            const __nv_bfloat16* Ap = (pass == 1) ? sA_lo : sA_hi;
            const int bp = (pass == 2) ? 1 : 0;
            const unsigned long long* Bf =
                g_Bfrag + (((size_t)(l * 2 + bp)) << 15) + (w * 4) * 32 + lane;
            unsigned long long bc[4];
            #pragma unroll
            for (int j = 0; j < 4; j++) bc[j] = Bf[j * 32];
            #pragma unroll 1
            for (int ks = 0; ks < 32; ks++) {
                unsigned long long bn[4] = {0, 0, 0, 0};
                if (ks < 31) {
                    #pragma unroll
                    for (int j = 0; j < 4; j++) bn[j] = Bf[(ks + 1) * 1024 + j * 32];
                }
                const int kc = ks * 16 + 2 * lq;
                uint32_t a[4][4];
                #pragma unroll
                for (int mt = 0; mt < 4; mt++) {
                    const __nv_bfloat16* Ar = Ap + (mt * 16 + gq) * AST + kc;
                    a[mt][0] = *(const uint32_t*)(Ar);
                    a[mt][1] = *(const uint32_t*)(Ar + 8 * AST);
                    a[mt][2] = *(const uint32_t*)(Ar + 8);
                    a[mt][3] = *(const uint32_t*)(Ar + 8 * AST + 8);
                }
                #pragma unroll
                for (int mt = 0; mt < 4; mt++)
                    #pragma unroll
                    for (int j = 0; j < 4; j++) {
                        uint32_t b0 = (uint32_t)bc[j];
                        uint32_t b1 = (uint32_t)(bc[j] >> 32);
                        MMA16816(acc[mt][j], a[mt], b0, b1);
                    }
                #pragma unroll
                for (int j = 0; j < 4; j++) bc[j] = bn[j];
            }
        }
        __syncthreads();   // all A reads done before epilogue rewrites A

        // epilogue: bias + relu + masks, write h32 (+A if l<2), pooled max
        const float* bias = (l == 0) ? bmp1 : (l == 1) ? bmp2 : bmp3;
        #pragma unroll
        for (int nti = 0; nti < 4; nti++) {
            #pragma unroll
            for (int par = 0; par < 2; par++) {
                const int col = w * 32 + nti * 8 + 2 * lq + par;
                const float bv = bias[col];
                float cm0 = 0.f, cm1 = 0.f;
                #pragma unroll
                for (int mt = 0; mt < 4; mt++) {
                    #pragma unroll
                    for (int rh = 0; rh < 2; rh++) {
                        int row = mt * 16 + gq + rh * 8;
                        int gi = row >> 5, n = row & 31;
                        float v = acc[mt][nti][rh * 2 + par] + bv;
                        bool ok = (n < NB) && (s_cnt[gi * 32 + n] != 0);
                        v = ok ? fmaxf(v, 0.f) : 0.f;
                        h32[row * H32ST + col] = v;
                        if (l < 2) {
                            unsigned short hb = bfhi(v);
                            sA_hi[row * AST + col] = __ushort_as_bfloat16(hb);
                            sA_lo[row * AST + col] = __float2bfloat16_rn(
                                v - __bfloat162float(__ushort_as_bfloat16(hb)));
                        }
                        if (gi == 0) cm0 = fmaxf(cm0, v); else cm1 = fmaxf(cm1, v);
                    }
                }
                cm0 = fmaxf(cm0, __shfl_xor_sync(0xffffffffu, cm0, 4));
                cm0 = fmaxf(cm0, __shfl_xor_sync(0xffffffffu, cm0, 8));
                cm0 = fmaxf(cm0, __shfl_xor_sync(0xffffffffu, cm0, 16));
                cm1 = fmaxf(cm1, __shfl_xor_sync(0xffffffffu, cm1, 4));
                cm1 = fmaxf(cm1, __shfl_xor_sync(0xffffffffu, cm1, 8));
                cm1 = fmaxf(cm1, __shfl_xor_sync(0xffffffffu, cm1, 16));
                if (gq == 0) {
                    g_gbuf[(2 * blk + 0) * 1024 + (l + 1) * D + col] = cm0;
                    g_gbuf[(2 * blk + 1) * 1024 + (l + 1) * D + col] = cm1;
                }
            }
        }
        __syncthreads();
    }
}

// ---------------------------------------------------------------------------
// Readout (unchanged): latent = g @ Wagg + b; mu/logvar.
// ---------------------------------------------------------------------------
__global__ void __launch_bounds__(256)
aux_kernel(const float* __restrict__ Wagg, const float* __restrict__ bagg,
           const float* __restrict__ Wmu,  const float* __restrict__ bmu,
           const float* __restrict__ Wvar, const float* __restrict__ bvar,
           float* __restrict__ out)
{
    __shared__ float sh_g[GAUX * 1024];
    __shared__ float sh_lat[GAUX * D];
    const int c  = threadIdx.x;
    const int g0 = blockIdx.x * GAUX;

    {
        const float4* src = (const float4*)(g_gbuf + g0 * 1024);
        float4* dst = (float4*)sh_g;
        #pragma unroll
        for (int i = 0; i < GAUX * 1024 / 4 / 256; i++)
            dst[i * 256 + c] = src[i * 256 + c];
    }
    __syncthreads();

    float lat[GAUX];
    {
        float bg = bagg[c];
        #pragma unroll
        for (int i = 0; i < GAUX; i++) lat[i] = bg;
    }
    for (int k4 = 0; k4 < 4 * D; k4 += 4) {
        float w0 = Wagg[(k4 + 0) * D + c];
        float w1 = Wagg[(k4 + 1) * D + c];
        float w2 = Wagg[(k4 + 2) * D + c];
        float w3 = Wagg[(k4 + 3) * D + c];
        #pragma unroll
        for (int i = 0; i < GAUX; i++) {
            float4 gv = *(const float4*)(sh_g + i * 1024 + k4);
            lat[i] = fmaf(gv.x, w0, fmaf(gv.y, w1, fmaf(gv.z, w2, fmaf(gv.w, w3, lat[i]))));
        }
    }
    __syncthreads();
    #pragma unroll
    for (int i = 0; i < GAUX; i++) sh_lat[i * D + c] = lat[i];
    __syncthreads();

    float mu[GAUX], lv[GAUX];
    {
        float bm_ = bmu[c], bv_ = bvar[c];
        #pragma unroll
        for (int i = 0; i < GAUX; i++) { mu[i] = bm_; lv[i] = bv_; }
    }
    for (int j4 = 0; j4 < D; j4 += 4) {
        float m0 = Wmu[(j4 + 0) * D + c],  m1 = Wmu[(j4 + 1) * D + c];
        float m2 = Wmu[(j4 + 2) * D + c],  m3 = Wmu[(j4 + 3) * D + c];
        float v0 = Wvar[(j4 + 0) * D + c], v1 = Wvar[(j4 + 1) * D + c];
        float v2 = Wvar[(j4 + 2) * D + c], v3 = Wvar[(j4 + 3) * D + c];
        #pragma unroll
        for (int i = 0; i < GAUX; i++) {
            float4 L = *(const float4*)(sh_lat + i * D + j4);
            mu[i] = fmaf(L.x, m0, fmaf(L.y, m1, fmaf(L.z, m2, fmaf(L.w, m3, mu[i]))));
            lv[i] = fmaf(L.x, v0, fmaf(L.y, v1, fmaf(L.z, v2, fmaf(L.w, v3, lv[i]))));
        }
    }
    #pragma unroll
    for (int i = 0; i < GAUX; i++) {
        out[(g0 + i) * D + c]          = mu[i];
        out[BG * D + (g0 + i) * D + c] = lv[i];
    }
}

// ---------------------------------------------------------------------------
extern "C" void kernel_launch(void* const* d_in, const int* in_sizes, int n_in,
                              void* d_out, int out_size)
{
    const float* geometry = (const float*)d_in[0];
    const int*   semantic = (const int*)d_in[1];
    const int*   eidx     = (const int*)d_in[2];
    const float* Wgeo = (const float*)d_in[4];
    const float* bgeo = (const float*)d_in[5];
    const float* emb  = (const float*)d_in[6];
    const float* Wlot = (const float*)d_in[7];
    const float* blot = (const float*)d_in[8];
    const float* Wmp1 = (const float*)d_in[9];
    const float* bmp1 = (const float*)d_in[10];
    const float* Wmp2 = (const float*)d_in[11];
    const float* bmp2 = (const float*)d_in[12];
    const float* Wmp3 = (const float*)d_in[13];
    const float* bmp3 = (const float*)d_in[14];
    const float* Wagg = (const float*)d_in[15];
    const float* bagg = (const float*)d_in[16];
    const float* Wmu  = (const float*)d_in[17];
    const float* bmu  = (const float*)d_in[18];
    const float* Wvar = (const float*)d_in[19];
    const float* bvar = (const float*)d_in[20];

    const int n_edges = in_sizes[2] / 2;
    const int* e_src = eidx;
    const int* e_dst = eidx + n_edges;

    // init: 17 MLP-fold blocks + 196608/256 = 768 pack blocks
    init_kernel<<<17 + 768, 256>>>(Wgeo, bgeo, emb, Wlot, blot, Wmp1, Wmp2, Wmp3);

    // smem: A_hi + A_lo (bf16) + h32 (fp32) + CSR/misc
    size_t smem_bytes = (size_t)2 * 64 * AST * 2          // A hi+lo
                      + (size_t)64 * H32ST * 4            // h32
                      + (size_t)(64 * 5 + 480) * 4        // ints
                      + (size_t)(64 + 300) * 4            // floats
                      + 64;
    cudaFuncSetAttribute(graph_kernel, cudaFuncAttributeMaxDynamicSharedMemorySize,
                         (int)smem_bytes);

    graph_kernel<<<BG / 2, 256, smem_bytes>>>(
        geometry, semantic, e_src, e_dst, Wlot, bmp1, bmp2, bmp3);

    aux_kernel<<<BG / GAUX, 256>>>(Wagg, bagg, Wmu, bmu, Wvar, bvar, (float*)d_out);
}